// round 1
// baseline (speedup 1.0000x reference)
#include <cuda_runtime.h>
#include <cuda_bf16.h>

// Problem constants: B=8, C=4, H=256, W=256
#define BB 8
#define CC 4
#define HH 256
#define WW 256
#define NPIX (BB*HH*WW)            // 524288
#define NBC  (BB*CC)               // 32
#define WORDS_PER_IMG (HH*WW/32)   // 2048
#define BIGD 512                   // H+W cap
#define PADV 0x3FFFFFFF

// Scratch (no dynamic allocation allowed). All fully rewritten each launch.
__device__ unsigned d_pbits[NBC * WORDS_PER_IMG];   // p_bin bits, per (b,c)
__device__ unsigned d_gbits[NBC * WORDS_PER_IMG];   // g_bin bits, per (b,c)
__device__ unsigned short d_gcol[4u * NBC * HH * WW]; // column 1D distance g, per family
__device__ int d_flags[4 * NBC];                    // mask.any() per (family, bc)
__device__ float d_partial[NBC * HH];               // per-(bc,h) partial sums

// ---------------------------------------------------------------------------
// Kernel 0: softmax + binarize + bit-pack masks
// grid: NPIX/256 blocks x 256 threads; warp spans 32 consecutive w of one row
// ---------------------------------------------------------------------------
__global__ void k_masks(const float* __restrict__ logits, const int* __restrict__ target) {
    int pid = blockIdx.x * 256 + threadIdx.x;   // 0..NPIX-1
    int b = pid >> 16;                          // H*W = 65536
    int rem = pid & 0xFFFF;                     // h*W + w

    float x0 = logits[(b * 4 + 0) * 65536 + rem];
    float x1 = logits[(b * 4 + 1) * 65536 + rem];
    float x2 = logits[(b * 4 + 2) * 65536 + rem];
    float x3 = logits[(b * 4 + 3) * 65536 + rem];
    float m = fmaxf(fmaxf(x0, x1), fmaxf(x2, x3));
    float e0 = expf(x0 - m), e1 = expf(x1 - m), e2 = expf(x2 - m), e3 = expf(x3 - m);
    float hs = 0.5f * (e0 + e1 + e2 + e3);      // p_c > 0.5  <=>  e_c > hs

    int tgt = target[pid];
    unsigned lane = threadIdx.x & 31;
    int widx = rem >> 5;                        // word index within image

    float ev[4] = {e0, e1, e2, e3};
#pragma unroll
    for (int c = 0; c < 4; ++c) {
        unsigned pb = __ballot_sync(0xFFFFFFFFu, ev[c] > hs);
        unsigned gb = __ballot_sync(0xFFFFFFFFu, tgt == c);
        if (lane == 0) {
            d_pbits[(b * 4 + c) * WORDS_PER_IMG + widx] = pb;
            d_gbits[(b * 4 + c) * WORDS_PER_IMG + widx] = gb;
        }
    }
}

// ---------------------------------------------------------------------------
// Kernel 1: column distance transform (two scans) per mask.
// grid: 128 blocks (one per mask: family f in {p,~p,g,~g} x 32 (b,c)),
// 256 threads (one per column).
// ---------------------------------------------------------------------------
__global__ void k_coldist() {
    int msk = blockIdx.x;          // 0..127
    int f = msk >> 5;              // family
    int bc = msk & 31;
    int w = threadIdx.x;

    const unsigned* bits = (f < 2 ? d_pbits : d_gbits) + bc * WORDS_PER_IMG;
    unsigned inv = (f & 1) ? 0xFFFFFFFFu : 0u;
    unsigned lm = 1u << (w & 31);
    int wword = w >> 5;
    unsigned short* g = d_gcol + (size_t)msk * (HH * WW);

    // downward scan: distance to nearest true at-or-above, capped at BIGD
    int d = BIGD;
    unsigned any = 0;
#pragma unroll 4
    for (int h = 0; h < HH; ++h) {
        unsigned word = bits[h * 8 + wword] ^ inv;
        any |= word;
        d = (word & lm) ? 0 : min(d + 1, BIGD);
        g[h * WW + w] = (unsigned short)d;
    }

    // mask.any() reduce (deterministic; all lanes in a warp see identical 'any')
    __shared__ unsigned s_any[8];
    if ((w & 31) == 0) s_any[w >> 5] = any;
    __syncthreads();
    if (w == 0) {
        unsigned a = 0;
#pragma unroll
        for (int k = 0; k < 8; ++k) a |= s_any[k];
        d_flags[msk] = (a != 0) ? 1 : 0;
    }

    // upward scan + combine
    d = BIGD;
#pragma unroll 4
    for (int h = HH - 1; h >= 0; --h) {
        unsigned word = bits[h * 8 + wword] ^ inv;
        d = (word & lm) ? 0 : min(d + 1, BIGD);
        int gv = g[h * WW + w];
        g[h * WW + w] = (unsigned short)min(gv, d);
    }
}

// ---------------------------------------------------------------------------
// Kernel 2: row lower-envelope (outward scan, early exit) + loss accumulation.
// grid: NBC*HH blocks ((b,c),h), 256 threads (one per pixel in row).
// ---------------------------------------------------------------------------
__global__ void k_loss(const float* __restrict__ logits, const int* __restrict__ target) {
    int bid = blockIdx.x;          // 0..8191
    int bc = bid >> 8;
    int h = bid & 255;
    int i = threadIdx.x;

    __shared__ int sg[4][3 * WW];  // [pad 256][real 256][pad 256]
    __shared__ int sflag[4];
    __shared__ float red[256];

#pragma unroll
    for (int f = 0; f < 4; ++f) {
        sg[f][i] = PADV;
        sg[f][2 * WW + i] = PADV;
        int gv = d_gcol[(((size_t)f * NBC + bc) * HH + h) * WW + i];
        sg[f][WW + i] = gv * gv;
    }
    if (i < 4) sflag[i] = d_flags[i * NBC + bc];
    __syncthreads();

    float dt[4];
#pragma unroll
    for (int f = 0; f < 4; ++f) {
        if (sflag[f]) {
            const int* gp = &sg[f][WW];
            int best = gp[i];
#pragma unroll 1
            for (int r = 1; r < WW; ++r) {
                int r2 = r * r;
                if (r2 >= best) break;
                best = min(best, r2 + gp[i - r]);
                best = min(best, r2 + gp[i + r]);
            }
            dt[f] = sqrtf((float)best);
        } else {
            dt[f] = 0.0f;
        }
    }
    float dp = dt[0] + dt[1];
    float dg = dt[2] + dt[3];
    float wgt = dp * dp + dg * dg;

    int b = bc >> 2, c = bc & 3;
    int rem = h * WW + i;
    float x0 = logits[(b * 4 + 0) * 65536 + rem];
    float x1 = logits[(b * 4 + 1) * 65536 + rem];
    float x2 = logits[(b * 4 + 2) * 65536 + rem];
    float x3 = logits[(b * 4 + 3) * 65536 + rem];
    float m = fmaxf(fmaxf(x0, x1), fmaxf(x2, x3));
    float e0 = expf(x0 - m), e1 = expf(x1 - m), e2 = expf(x2 - m), e3 = expf(x3 - m);
    float s = e0 + e1 + e2 + e3;
    float ec = (c == 0) ? e0 : (c == 1) ? e1 : (c == 2) ? e2 : e3;
    float p = ec / s;

    int tgt = target[b * 65536 + rem];
    float oh = (tgt == c) ? 1.0f : 0.0f;
    float diff = p - oh;
    float v = diff * diff * wgt;

    red[i] = v;
    __syncthreads();
#pragma unroll
    for (int st = 128; st > 0; st >>= 1) {
        if (i < st) red[i] += red[i + st];
        __syncthreads();
    }
    if (i == 0) d_partial[bid] = red[0];
}

// ---------------------------------------------------------------------------
// Kernel 3: deterministic final reduction + scale
// ---------------------------------------------------------------------------
__global__ void k_final(float* __restrict__ out) {
    int i = threadIdx.x;   // 256 threads
    float s = 0.0f;
    for (int k = i; k < NBC * HH; k += 256) s += d_partial[k];
    __shared__ float red[256];
    red[i] = s;
    __syncthreads();
#pragma unroll
    for (int st = 128; st > 0; st >>= 1) {
        if (i < st) red[i] += red[i + st];
        __syncthreads();
    }
    // denom = fp32(B*H*W) + 1e-6 == 524288.0 in fp32; loss = total / (denom * C)
    if (i == 0) out[0] = red[0] * (1.0f / (524288.0f * 4.0f));
}

extern "C" void kernel_launch(void* const* d_in, const int* in_sizes, int n_in,
                              void* d_out, int out_size) {
    const float* logits = (const float*)d_in[0];
    const int* target = (const int*)d_in[1];
    float* out = (float*)d_out;
    (void)in_sizes; (void)n_in; (void)out_size;

    k_masks<<<NPIX / 256, 256>>>(logits, target);
    k_coldist<<<4 * NBC, WW>>>();
    k_loss<<<NBC * HH, WW>>>(logits, target);
    k_final<<<1, 256>>>(out);
}

// round 2
// speedup vs baseline: 1.0448x; 1.0448x over previous
#include <cuda_runtime.h>
#include <cuda_bf16.h>

// B=8, C=4, H=256, W=256
#define HH 256
#define WW 256
#define NBC 32                 // B*C
#define WPI 2048               // bit-words per image (256*256/32)
#define PADV (1<<28)

// Scratch (static; fully rewritten every launch)
__device__ unsigned d_pbits[NBC * WPI];            // p_bin bits
__device__ unsigned d_gbits[NBC * WPI];            // g_bin bits
__device__ unsigned char d_val[2 * NBC * HH * WW]; // paired column distance (u8)
__device__ unsigned char d_cemp[2 * NBC * WW];     // per-column empty flags (bit0=m,bit1=~m)
__device__ int d_flags[4 * NBC];                   // image-level mask.any() per family
__device__ unsigned long long d_acc;               // fixed-point loss accumulator
__device__ unsigned int d_count;                   // last-block counter

// ---------------------------------------------------------------------------
// Kernel 0: softmax threshold + bit-pack masks; resets accumulators/flags
// ---------------------------------------------------------------------------
__global__ void k_masks(const float* __restrict__ logits, const int* __restrict__ target) {
    if (blockIdx.x == 0) {
        if (threadIdx.x < 128) d_flags[threadIdx.x] = 0;
        if (threadIdx.x == 0) { d_acc = 0ull; d_count = 0u; }
    }
    int pid = blockIdx.x * 256 + threadIdx.x;
    int b = pid >> 16, rem = pid & 0xFFFF;
    const float* lb = logits + b * 262144 + rem;
    float x0 = lb[0], x1 = lb[65536], x2 = lb[131072], x3 = lb[196608];
    float m = fmaxf(fmaxf(x0, x1), fmaxf(x2, x3));
    float e0 = __expf(x0 - m), e1 = __expf(x1 - m), e2 = __expf(x2 - m), e3 = __expf(x3 - m);
    float hs = 0.5f * (e0 + e1 + e2 + e3);    // p_c > 0.5  <=>  e_c > hs
    int tgt = target[pid];
    unsigned lane = threadIdx.x & 31;
    int widx = rem >> 5;
    float ev[4] = {e0, e1, e2, e3};
#pragma unroll
    for (int c = 0; c < 4; ++c) {
        unsigned pb = __ballot_sync(0xFFFFFFFFu, ev[c] > hs);
        unsigned gb = __ballot_sync(0xFFFFFFFFu, tgt == c);
        if (lane == 0) {
            d_pbits[(b * 4 + c) * WPI + widx] = pb;
            d_gbits[(b * 4 + c) * WPI + widx] = gb;
        }
    }
}

// ---------------------------------------------------------------------------
// Kernel 1: paired column distance transform. One pass computes BOTH families
// (m and ~m) of a pair; stores only the relevant-polarity distance (u8).
// grid: 2 pairs x 32 bc x 2 column-tiles = 128 blocks, 128 threads (1 column each)
// ---------------------------------------------------------------------------
__global__ void k_coldist() {
    int id = blockIdx.x;
    int tile = id & 1;
    int bc   = (id >> 1) & 31;
    int pair = id >> 6;
    int col  = tile * 128 + threadIdx.x;

    const unsigned* bits = (pair ? d_gbits : d_pbits) + bc * WPI;
    unsigned lm = 1u << (col & 31);
    int wword = col >> 5;
    unsigned char* val = d_val + (pair * NBC + bc) * 65536 + col;

    // downward: distance since last 1-bit (dm) and since last 0-bit (dn)
    int dm = 512, dn = 512, om = 0, on = 0;
#pragma unroll 4
    for (int h = 0; h < HH; ++h) {
        unsigned w = bits[h * 8 + wword];
        int bit = (w & lm) ? 1 : 0;
        om |= bit; on |= bit ^ 1;
        dm = bit ? 0 : min(dm + 1, 512);
        dn = bit ? min(dn + 1, 512) : 0;
        int sv = bit ? dn : dm;
        val[h * WW] = (unsigned char)min(sv, 255);
    }
    // upward + combine
    int um = 512, un = 512;
#pragma unroll 4
    for (int h = HH - 1; h >= 0; --h) {
        unsigned w = bits[h * 8 + wword];
        int bit = (w & lm) ? 1 : 0;
        um = bit ? 0 : min(um + 1, 512);
        un = bit ? min(un + 1, 512) : 0;
        int sv = min(bit ? un : um, 255);
        int old = val[h * WW];
        val[h * WW] = (unsigned char)min(old, sv);
    }
    d_cemp[(pair * NBC + bc) * WW + col] = (unsigned char)((om ? 0 : 1) | (on ? 0 : 2));

    unsigned bm = __ballot_sync(0xFFFFFFFFu, om);
    unsigned bn = __ballot_sync(0xFFFFFFFFu, on);
    if ((threadIdx.x & 31) == 0) {
        if (bm) atomicOr(&d_flags[(pair * 2 + 0) * NBC + bc], 1);
        if (bn) atomicOr(&d_flags[(pair * 2 + 1) * NBC + bc], 1);
    }
}

// ---------------------------------------------------------------------------
// Kernel 2: row lower-envelope (outward scan, early exit) + loss + final sum.
// grid: 32 bc x 64 row-groups (4 rows each) = 2048 blocks, 256 threads.
// ---------------------------------------------------------------------------
__global__ void k_loss(const float* __restrict__ logits, const int* __restrict__ target,
                       float* __restrict__ out) {
    int bc = blockIdx.x >> 6;
    int h0 = (blockIdx.x & 63) * 4;
    int i = threadIdx.x;
    int b = bc >> 2, c = bc & 3;

    __shared__ int sg[4][3 * WW];  // [pad | data | pad]
    __shared__ int sflag[4];
    __shared__ float swarp[8];

#pragma unroll
    for (int f = 0; f < 4; ++f) { sg[f][i] = PADV; sg[f][2 * WW + i] = PADV; }
    if (i < 4) sflag[i] = d_flags[i * NBC + bc];

    int cep = d_cemp[(0 * NBC + bc) * WW + i];
    int ceg = d_cemp[(1 * NBC + bc) * WW + i];
    int sh = i & 31, wi = i >> 5;
    const unsigned* pb = d_pbits + bc * WPI;
    const unsigned* gb = d_gbits + bc * WPI;
    const unsigned char* vp = d_val + (0 * NBC + bc) * 65536 + i;
    const unsigned char* vg = d_val + (1 * NBC + bc) * 65536 + i;

    float acc = 0.0f;
    for (int r = 0; r < 4; ++r) {
        int h = h0 + r;
        int bitp = (pb[h * 8 + wi] >> sh) & 1;
        int bitg = (gb[h * 8 + wi] >> sh) & 1;
        int valp = vp[h * WW];
        int valg = vg[h * WW];
        int g0 = bitp ? 0 : ((cep & 1) ? 512 : valp);
        int g1 = bitp ? ((cep & 2) ? 512 : valp) : 0;
        int g2 = bitg ? 0 : ((ceg & 1) ? 512 : valg);
        int g3 = bitg ? ((ceg & 2) ? 512 : valg) : 0;
        sg[0][WW + i] = g0 * g0;
        sg[1][WW + i] = g1 * g1;
        sg[2][WW + i] = g2 * g2;
        sg[3][WW + i] = g3 * g3;
        __syncthreads();

        float dt[4];
#pragma unroll
        for (int f = 0; f < 4; ++f) {
            if (sflag[f]) {
                const int* gp = &sg[f][WW];
                int best = gp[i];
                int rr = 1, r2 = 1;
#pragma unroll 1
                while (r2 < best) {
                    best = min(best, r2 + gp[i - rr]);
                    best = min(best, r2 + gp[i + rr]);
                    r2 += 2 * rr + 1; rr++;
                }
                dt[f] = sqrtf((float)best);
            } else dt[f] = 0.0f;
        }
        __syncthreads();

        float dp = dt[0] + dt[1], dg = dt[2] + dt[3];
        float wgt = dp * dp + dg * dg;
        int rem = h * WW + i;
        const float* lb = logits + b * 262144 + rem;
        float x0 = lb[0], x1 = lb[65536], x2 = lb[131072], x3 = lb[196608];
        float m = fmaxf(fmaxf(x0, x1), fmaxf(x2, x3));
        float e0 = __expf(x0 - m), e1 = __expf(x1 - m), e2 = __expf(x2 - m), e3 = __expf(x3 - m);
        float s = e0 + e1 + e2 + e3;
        float ec = (c == 0) ? e0 : (c == 1) ? e1 : (c == 2) ? e2 : e3;
        float p = __fdividef(ec, s);
        float oh = (target[b * 65536 + rem] == c) ? 1.0f : 0.0f;
        float d = p - oh;
        acc += d * d * wgt;
    }

    // deterministic block reduce (fixed tree) -> fixed-point global atomic
#pragma unroll
    for (int o = 16; o > 0; o >>= 1) acc += __shfl_down_sync(0xFFFFFFFFu, acc, o);
    if ((i & 31) == 0) swarp[i >> 5] = acc;
    __syncthreads();
    if (i < 32) {
        float v = (i < 8) ? swarp[i] : 0.0f;
#pragma unroll
        for (int o = 4; o > 0; o >>= 1) v += __shfl_down_sync(0xFFFFFFFFu, v, o);
        if (i == 0) {
            long long ll = __double2ll_rn((double)v * 1048576.0);
            atomicAdd(&d_acc, (unsigned long long)ll);
            __threadfence();
            unsigned old = atomicAdd(&d_count, 1u);
            if (old == gridDim.x - 1) {
                unsigned long long tot = atomicAdd(&d_acc, 0ull);
                double t = (double)(long long)tot * (1.0 / 1048576.0);
                out[0] = (float)(t / (524288.0 * 4.0));
            }
        }
    }
}

extern "C" void kernel_launch(void* const* d_in, const int* in_sizes, int n_in,
                              void* d_out, int out_size) {
    const float* logits = (const float*)d_in[0];
    const int* target = (const int*)d_in[1];
    float* out = (float*)d_out;
    (void)in_sizes; (void)n_in; (void)out_size;

    k_masks<<<2048, 256>>>(logits, target);
    k_coldist<<<128, 128>>>();
    k_loss<<<2048, 256>>>(logits, target, out);
}

// round 3
// speedup vs baseline: 1.2984x; 1.2427x over previous
#include <cuda_runtime.h>
#include <cuda_bf16.h>

// B=8, C=4, H=256, W=256
#define HH 256
#define WW 256

// Static scratch (fully rewritten every launch)
__device__ unsigned char d_pk[8 * 65536];        // per-pixel packed bits: p classes 0-3 (bits 0-3), g (bits 4-7)
__device__ float4 d_err4[8 * 65536];             // per-pixel (p_c - oh_c)^2 for c=0..3
__device__ unsigned char d_vdn[2 * 32 * 65536];  // downward column dist-to-opposite (mask m, bc, h, w)
__device__ unsigned char d_vup[2 * 32 * 65536];  // upward column dist-to-opposite
__device__ int d_flags[4 * 32];                  // [(m*2+s)*32+bc] : set {bit==s} nonempty
__device__ unsigned long long d_acc;             // fixed-point loss accumulator
__device__ unsigned d_count;                     // last-block counter

// ---------------------------------------------------------------------------
// K0: softmax once per pixel -> packed mask bits + per-class squared error
// ---------------------------------------------------------------------------
__global__ void k_masks(const float* __restrict__ logits, const int* __restrict__ target) {
    int pid = blockIdx.x * 256 + threadIdx.x;
    if (blockIdx.x == 0) {
        if (threadIdx.x < 128) d_flags[threadIdx.x] = 0;
        if (threadIdx.x == 0) { d_acc = 0ull; d_count = 0u; }
    }
    int b = pid >> 16, rem = pid & 0xFFFF;
    const float* lb = logits + b * 262144 + rem;
    float x0 = lb[0], x1 = lb[65536], x2 = lb[131072], x3 = lb[196608];
    float m = fmaxf(fmaxf(x0, x1), fmaxf(x2, x3));
    float e0 = __expf(x0 - m), e1 = __expf(x1 - m), e2 = __expf(x2 - m), e3 = __expf(x3 - m);
    float s = e0 + e1 + e2 + e3;
    float hs = 0.5f * s;                 // p_c > 0.5  <=>  e_c > hs
    float inv = __frcp_rn(s);
    int tgt = target[pid];

    unsigned pk = (e0 > hs ? 1u : 0u) | (e1 > hs ? 2u : 0u) |
                  (e2 > hs ? 4u : 0u) | (e3 > hs ? 8u : 0u) | (16u << tgt);
    d_pk[pid] = (unsigned char)pk;

    float p0 = e0 * inv, p1 = e1 * inv, p2 = e2 * inv, p3 = e3 * inv;
    float d0 = p0 - ((tgt == 0) ? 1.0f : 0.0f);
    float d1 = p1 - ((tgt == 1) ? 1.0f : 0.0f);
    float d2 = p2 - ((tgt == 2) ? 1.0f : 0.0f);
    float d3 = p3 - ((tgt == 3) ? 1.0f : 0.0f);
    d_err4[pid] = make_float4(d0 * d0, d1 * d1, d2 * d2, d3 * d3);
}

// ---------------------------------------------------------------------------
// K1: single-direction column distance-to-opposite scans.
// grid: 256 blocks = dir(2) x mask(2) x bc(32) x col-tile(2), 128 threads.
// ---------------------------------------------------------------------------
__global__ void k_coldist() {
    int id = blockIdx.x;
    int tile = id & 1;
    int bc = (id >> 1) & 31;
    int mm = (id >> 6) & 1;
    int dir = id >> 7;
    int col = tile * 128 + threadIdx.x;
    int b = bc >> 2, c = bc & 3;

    const unsigned char* pk = d_pk + b * 65536 + col;
    int sh = mm * 4 + c;
    unsigned char* out = (dir ? d_vup : d_vdn) + (mm * 32 + bc) * 65536 + col;

    int dm = 255, dn = 255;          // dist since last 1-bit / last 0-bit (capped)
    if (dir == 0) {
        unsigned om = 0, on = 0;
#pragma unroll 8
        for (int h = 0; h < HH; ++h) {
            int bit = (pk[h * 256] >> sh) & 1;
            om |= bit; on |= bit ^ 1;
            dm = bit ? 0 : min(dm + 1, 255);
            dn = bit ? min(dn + 1, 255) : 0;
            out[h * 256] = (unsigned char)(bit ? dn : dm);   // dist to opposite polarity
        }
        unsigned bm = __ballot_sync(0xFFFFFFFFu, om);
        unsigned bn = __ballot_sync(0xFFFFFFFFu, on);
        if ((threadIdx.x & 31) == 0) {
            if (bm) atomicOr(&d_flags[(mm * 2 + 1) * 32 + bc], 1);  // {bit==1} nonempty
            if (bn) atomicOr(&d_flags[(mm * 2 + 0) * 32 + bc], 1);  // {bit==0} nonempty
        }
    } else {
#pragma unroll 8
        for (int h = HH - 1; h >= 0; --h) {
            int bit = (pk[h * 256] >> sh) & 1;
            dm = bit ? 0 : min(dm + 1, 255);
            dn = bit ? min(dn + 1, 255) : 0;
            out[h * 256] = (unsigned char)(bit ? dn : dm);
        }
    }
}

// ---------------------------------------------------------------------------
// K2: branch-free row lower-envelope + loss + global reduction.
// grid: 2048 blocks = (b, h), 256 threads (one pixel each).
// ---------------------------------------------------------------------------
__global__ void k_loss(float* __restrict__ out) {
    int b = blockIdx.x >> 8;
    int h = blockIdx.x & 255;
    int i = threadIdx.x;

    // 16 arrays [(c*2+m)*2+pol][264]: entry j+4 = (bit_j==pol) ? val_j : 0; pads=255
    __shared__ unsigned char sv[16 * 264];
    __shared__ int sflag[16];
    __shared__ float swarp[8];

    if (i < 128) {                       // pad entries: [0..4) and [260..264) per array
        int a = i >> 3, slot = i & 7;
        sv[a * 264 + (slot < 4 ? slot : 256 + slot)] = 255;
    }
    if (i < 16) {                        // sflag[(c*2+m)*2+s] = {bit==s} nonempty for (b,c,m)
        int c = i >> 2, m = (i >> 1) & 1, s = i & 1;
        sflag[i] = d_flags[(m * 2 + s) * 32 + b * 4 + c];
    }

    int pix = b * 65536 + h * 256 + i;
    unsigned pk = d_pk[pix];

    int bits[8], vcol[8];
#pragma unroll
    for (int c = 0; c < 4; ++c) {
        int bp = (pk >> c) & 1;
        int bg = (pk >> (4 + c)) & 1;
        int basep = (b * 4 + c) * 65536 + h * 256 + i;
        int baseg = basep + 32 * 65536;
        int vp = min((int)d_vdn[basep], (int)d_vup[basep]);
        int vg = min((int)d_vdn[baseg], (int)d_vup[baseg]);
        sv[((c * 2 + 0) * 2 + bp) * 264 + 4 + i] = (unsigned char)vp;
        sv[((c * 2 + 0) * 2 + (bp ^ 1)) * 264 + 4 + i] = 0;
        sv[((c * 2 + 1) * 2 + bg) * 264 + 4 + i] = (unsigned char)vg;
        sv[((c * 2 + 1) * 2 + (bg ^ 1)) * 264 + 4 + i] = 0;
        bits[2 * c] = bp; bits[2 * c + 1] = bg;
        vcol[2 * c] = vp; vcol[2 * c + 1] = vg;
    }
    __syncthreads();

    int d2[8];
#pragma unroll
    for (int k = 0; k < 8; ++k) {
        int c = k >> 1, m = k & 1;
        int pol = bits[k];
        int abase = ((c * 2 + m) * 2 + pol) * 264;
        const unsigned char* ap = &sv[abase + 4 + i];
        int v = vcol[k];
        int best = v * v;
#pragma unroll
        for (int r = 1; r <= 4; ++r) {          // branch-free core scan
            int a = ap[-r], bb = ap[r];
            best = min(best, a * a + r * r);
            best = min(best, bb * bb + r * r);
        }
        if (__any_sync(0xFFFFFFFFu, best > 25)) {   // rare, warp-uniform fallback
            int r = 5;
            while (__any_sync(0xFFFFFFFFu, r * r < best)) {
                int jl = max(i - r, -4), jr = min(i + r, 259);
                int a = sv[abase + 4 + jl];
                int bb = sv[abase + 4 + jr];
                best = min(best, a * a + r * r);
                best = min(best, bb * bb + r * r);
                ++r;
            }
        }
        // needed family = {bit == pol^1}; empty mask -> dt contributes 0
        d2[k] = sflag[(c * 2 + m) * 2 + (pol ^ 1)] ? best : 0;
    }

    float4 e4 = d_err4[pix];
    float acc = e4.x * (float)(d2[0] + d2[1])
              + e4.y * (float)(d2[2] + d2[3])
              + e4.z * (float)(d2[4] + d2[5])
              + e4.w * (float)(d2[6] + d2[7]);

    // deterministic block reduce -> fixed-point global atomic
#pragma unroll
    for (int o = 16; o > 0; o >>= 1) acc += __shfl_down_sync(0xFFFFFFFFu, acc, o);
    if ((i & 31) == 0) swarp[i >> 5] = acc;
    __syncthreads();
    if (i < 32) {
        float v = (i < 8) ? swarp[i] : 0.0f;
#pragma unroll
        for (int o = 4; o > 0; o >>= 1) v += __shfl_down_sync(0xFFFFFFFFu, v, o);
        if (i == 0) {
            long long ll = __double2ll_rn((double)v * 1048576.0);
            atomicAdd(&d_acc, (unsigned long long)ll);
            __threadfence();
            unsigned old = atomicAdd(&d_count, 1u);
            if (old == gridDim.x - 1) {
                unsigned long long tot = atomicAdd(&d_acc, 0ull);
                double t = (double)(long long)tot * (1.0 / 1048576.0);
                out[0] = (float)(t / (524288.0 * 4.0));
            }
        }
    }
}

extern "C" void kernel_launch(void* const* d_in, const int* in_sizes, int n_in,
                              void* d_out, int out_size) {
    const float* logits = (const float*)d_in[0];
    const int* target = (const int*)d_in[1];
    float* out = (float*)d_out;
    (void)in_sizes; (void)n_in; (void)out_size;

    k_masks<<<2048, 256>>>(logits, target);
    k_coldist<<<256, 128>>>();
    k_loss<<<2048, 256>>>(out);
}